// round 14
// baseline (speedup 1.0000x reference)
#include <cuda_runtime.h>
#include <cstdint>

// loss = dot(colsum(a), colsum(b)),  a,b: [16384, 512] fp32  (2*LAMBD = 1.0)
// Champion shape (256 CTAs x 512 thr, scalar coalesced, unroll-16) with:
//  - ld.global.nc (non-coherent read-only path)
//  - prefetch.global.L2 at +16 rows (register-free MLP past ptxas's batch-8 cap)
//  - b loads carry L2::evict_last hint (small confirmed win)
// Epilogue: atomics -> last-block ticket -> dot + state reset.

#define ROWS 16384
#define COLS 512
#define NBLK 256
#define TPB  512
#define RPB  (ROWS / NBLK)   // 64 rows per block (compile-time)
#define PFD  16              // prefetch distance in rows

__device__ float g_sa[COLS];          // zero-init at module load; re-zeroed each call
__device__ float g_sb[COLS];
__device__ unsigned int g_ticket;

__device__ __forceinline__ uint64_t mk_evict_last_policy() {
    uint64_t pol;
    asm volatile("createpolicy.fractional.L2::evict_last.b64 %0, 1.0;" : "=l"(pol));
    return pol;
}
__device__ __forceinline__ float ldg_nc(const float* p) {
    float v;
    asm volatile("ld.global.nc.f32 %0, [%1];" : "=f"(v) : "l"(p));
    return v;
}
__device__ __forceinline__ float ldg_nc_keep(const float* p, uint64_t pol) {
    float v;
    asm volatile("ld.global.nc.L2::cache_hint.f32 %0, [%1], %2;"
                 : "=f"(v) : "l"(p), "l"(pol));
    return v;
}
__device__ __forceinline__ void pf_l2(const float* p) {
    asm volatile("prefetch.global.L2 [%0];" :: "l"(p));
}

__global__ __launch_bounds__(TPB) void fused_kernel(const float* __restrict__ a,
                                                    const float* __restrict__ b,
                                                    float* __restrict__ out) {
    const int c  = threadIdx.x;              // column 0..511 (coalesced across warp)
    const int r0 = blockIdx.x * RPB;

    const uint64_t pol = mk_evict_last_policy();
    const float* pa = a + (size_t)r0 * COLS + c;
    const float* pb = b + (size_t)r0 * COLS + c;

    float sa = 0.0f, sb = 0.0f;
#pragma unroll 16
    for (int r = 0; r < RPB; ++r) {          // constant trip count 64
        pf_l2(pa + (size_t)(r + PFD) * COLS);           // register-free MLP
        pf_l2(pb + (size_t)(r + PFD) * COLS);
        sa += ldg_nc(pa + (size_t)r * COLS);            // a: stream (nc path)
        sb += ldg_nc_keep(pb + (size_t)r * COLS, pol);  // b: pinned evict_last
    }
    atomicAdd(&g_sa[c], sa);
    atomicAdd(&g_sb[c], sb);

    // ---- last-block-done ticket ----
    __threadfence();                         // release
    __shared__ bool is_last;
    if (c == 0) {
        unsigned int t = atomicAdd(&g_ticket, 1u);
        is_last = (t == (unsigned)(gridDim.x - 1));
    }
    __syncthreads();
    if (!is_last) return;

    __threadfence();                         // acquire

    float va = __ldcg(&g_sa[c]);
    float vb = __ldcg(&g_sb[c]);
    g_sa[c] = 0.0f;                          // reset for next graph replay
    g_sb[c] = 0.0f;

    float v = va * vb;
    __shared__ float red[16];
#pragma unroll
    for (int o = 16; o > 0; o >>= 1)
        v += __shfl_xor_sync(0xffffffffu, v, o);
    if ((c & 31) == 0) red[c >> 5] = v;
    __syncthreads();
    if (c < 16) {
        float w = red[c];
#pragma unroll
        for (int o = 8; o > 0; o >>= 1)
            w += __shfl_xor_sync(0xffffu, w, o);
        if (c == 0) {
            out[0] = w;                      // 2 * LAMBD = 1.0
            g_ticket = 0u;
        }
    }
}

extern "C" void kernel_launch(void* const* d_in, const int* in_sizes, int n_in,
                              void* d_out, int out_size) {
    const float* a = (const float*)d_in[0];
    const float* b = (const float*)d_in[1];
    float* out = (float*)d_out;

    fused_kernel<<<NBLK, TPB>>>(a, b, out);
}

// round 15
// speedup vs baseline: 1.1626x; 1.1626x over previous
#include <cuda_runtime.h>
#include <cstdint>

// loss = dot(colsum(a), colsum(b)),  a,b: [16384, 512] fp32  (2*LAMBD = 1.0)
// Champion mainloop (256 CTAs x 512 thr, scalar coalesced, unroll-16,
// b pinned L2::evict_last) + tail-shaved epilogue:
//   red.global colsum adds -> acq_rel ticket -> single-warp finalize + reset.

#define ROWS 16384
#define COLS 512
#define NBLK 256
#define TPB  512
#define RPB  (ROWS / NBLK)   // 64 rows per block (compile-time)

__device__ float g_sa[COLS];          // zero-init at module load; re-zeroed each call
__device__ float g_sb[COLS];
__device__ unsigned int g_ticket;

__device__ __forceinline__ uint64_t mk_evict_last_policy() {
    uint64_t pol;
    asm volatile("createpolicy.fractional.L2::evict_last.b64 %0, 1.0;" : "=l"(pol));
    return pol;
}
__device__ __forceinline__ float ldg_keep(const float* p, uint64_t pol) {
    float v;
    asm volatile("ld.global.L2::cache_hint.f32 %0, [%1], %2;"
                 : "=f"(v) : "l"(p), "l"(pol));
    return v;
}
__device__ __forceinline__ void red_add(float* p, float v) {
    asm volatile("red.global.add.f32 [%0], %1;" :: "l"(p), "f"(v) : "memory");
}
__device__ __forceinline__ unsigned int ticket_acq_rel(unsigned int* p) {
    unsigned int old;
    asm volatile("atom.acq_rel.gpu.global.add.u32 %0, [%1], 1;"
                 : "=r"(old) : "l"(p) : "memory");
    return old;
}

__global__ __launch_bounds__(TPB) void fused_kernel(const float* __restrict__ a,
                                                    const float* __restrict__ b,
                                                    float* __restrict__ out) {
    const int c  = threadIdx.x;              // column 0..511 (coalesced across warp)
    const int r0 = blockIdx.x * RPB;

    const uint64_t pol = mk_evict_last_policy();
    const float* pa = a + (size_t)r0 * COLS + c;
    const float* pb = b + (size_t)r0 * COLS + c;

    float sa = 0.0f, sb = 0.0f;
#pragma unroll 16
    for (int r = 0; r < RPB; ++r) {          // constant trip count 64
        sa += pa[(size_t)r * COLS];          // a: default policy (stream)
        sb += ldg_keep(pb + (size_t)r * COLS, pol);  // b: pinned evict_last
    }
    red_add(&g_sa[c], sa);                   // fire-and-forget REDG
    red_add(&g_sb[c], sb);

    // ---- last-block-done ticket (acq_rel orders the REDGs above) ----
    __shared__ bool is_last;
    if (c == 0) {
        __threadfence();                     // release: REDGs visible before ticket
        unsigned int t = ticket_acq_rel(&g_ticket);
        is_last = (t == (unsigned)(gridDim.x - 1));
    }
    __syncthreads();
    if (!is_last) return;

    __threadfence();                         // acquire side

    float va = __ldcg(&g_sa[c]);
    float vb = __ldcg(&g_sb[c]);
    g_sa[c] = 0.0f;                          // reset for next graph replay
    g_sb[c] = 0.0f;

    float v = va * vb;
    __shared__ float red[16];
#pragma unroll
    for (int o = 16; o > 0; o >>= 1)
        v += __shfl_xor_sync(0xffffffffu, v, o);
    if ((c & 31) == 0) red[c >> 5] = v;
    __syncthreads();
    if (c < 16) {
        float w = red[c];
#pragma unroll
        for (int o = 8; o > 0; o >>= 1)
            w += __shfl_xor_sync(0xffffu, w, o);
        if (c == 0) {
            out[0] = w;                      // 2 * LAMBD = 1.0
            g_ticket = 0u;
        }
    }
}

extern "C" void kernel_launch(void* const* d_in, const int* in_sizes, int n_in,
                              void* d_out, int out_size) {
    const float* a = (const float*)d_in[0];
    const float* b = (const float*)d_in[1];
    float* out = (float*)d_out;

    fused_kernel<<<NBLK, TPB>>>(a, b, out);
}